// round 15
// baseline (speedup 1.0000x reference)
#include <cuda_runtime.h>
#include <stdint.h>

typedef unsigned long long u64;
#define EPSV 1e-5f

// smem (floats): sIn 2x(8ci x 18rows x 40cols)=11520 | sW 2x1152=2304 | sStat 512
#define CI_STRIDE  720
#define BUF_STRIDE 5760
#define SW_OFF     11520
#define SSTAT_OFF  13824
#define SMEM_FL    14336
#define SMEM_BYTES (SMEM_FL * 4)

__device__ float  g_C1[2][(size_t)64 * 64 * 1024];
__device__ float  g_P [2][(size_t)8 * 64 * 64 * 1024];
__device__ float  g_Xr [(size_t)64 * 64 * 1024];
__device__ float  g_N1r[(size_t)64 * 64 * 1024];
__device__ float  g_N2r[(size_t)64 * 64 * 1024];
__device__ float2 g_part1[2][64 * 128];          // [c][b*2+strip]
__device__ float2 g_part2[2][8 * 64 * 128];      // [k][c][b*2+strip]
__device__ float  g_scale1[2][64], g_shift1[2][64];
__device__ float  g_scaleP[2][8 * 64];
__device__ float  g_biasP[2][64];
__device__ float  g_m1v[64], g_cmv[64];
__device__ float  g_Wt[(size_t)8 * 32 * 1152];   // [set][ocb*8+cc][r=ci*9+tap][16 oc]

__device__ __forceinline__ u64 fma2(u64 a, u64 b, u64 c) {
    u64 d; asm("fma.rn.f32x2 %0, %1, %2, %3;" : "=l"(d) : "l"(a), "l"(b), "l"(c)); return d;
}
__device__ __forceinline__ u64 pack2(float x, float y) {
    u64 d; asm("mov.b64 %0, {%1, %2};" : "=l"(d) : "f"(x), "f"(y)); return d;
}
__device__ __forceinline__ float2 unpack2(u64 v) {
    float2 r; asm("mov.b64 {%0, %1}, %2;" : "=f"(r.x), "=f"(r.y) : "l"(v)); return r;
}
__device__ __forceinline__ void cpa16(uint32_t s, const float* g) {
    asm volatile("cp.async.cg.shared.global [%0], [%1], 16;" :: "r"(s), "l"(g));
}
__device__ __forceinline__ void cpa_commit() { asm volatile("cp.async.commit_group;"); }
template <int N> __device__ __forceinline__ void cpa_wait() {
    asm volatile("cp.async.wait_group %0;" :: "n"(N));
}

// 16-value butterfly + cross-half fold: lanes 0..15 end with full 32-lane sum
// of v[lane]; result returned as scalar.
__device__ __forceinline__ float warp_reduce16(float* v, int lane) {
#pragma unroll
    for (int d = 8; d >= 1; d >>= 1)
#pragma unroll
        for (int i = 0; i < d; ++i) {
            float mine = (lane & d) ? v[i + d] : v[i];
            float give = (lane & d) ? v[i]     : v[i + d];
            v[i] = mine + __shfl_xor_sync(0xffffffffu, give, d);
        }
    float r = v[0];
    r += __shfl_xor_sync(0xffffffffu, r, 16);
    return r;
}

// ------------------------------ prep kernels -------------------------------
__global__ void prep_small(const float* __restrict__ a1, const float* __restrict__ a2) {
    int c = threadIdx.x, g = c >> 3;
    float s1 = 0.f, s2 = 0.f;
    for (int i = g; i < 8; ++i) { s1 += a1[i]; s2 += a2[i]; }
    g_m1v[c] = s1; g_cmv[c] = s1 * s2;
}

__global__ void relux_kernel(const float* __restrict__ x) {   // <<<4096,256>>> float4
    size_t i = (size_t)blockIdx.x * 256 + threadIdx.x;
    float4 v = reinterpret_cast<const float4*>(x)[i];
    v.x = fmaxf(v.x, 0.f); v.y = fmaxf(v.y, 0.f);
    v.z = fmaxf(v.z, 0.f); v.w = fmaxf(v.w, 0.f);
    reinterpret_cast<float4*>(g_Xr)[i] = v;
}

// sets: 0:W1_0 1:W1_1 2:W2_0 3:W2_1 4:W1_4 5:W1_5 6:W2_4 7:W2_5
__global__ void wtrans_kernel(const float* p0, const float* p1, const float* p2, const float* p3,
                              const float* p4, const float* p5, const float* p6, const float* p7) {
    int setid = blockIdx.x >> 5;            // <<<256,256>>>
    int blk = blockIdx.x & 31;
    int ocb = blk >> 3, cc = blk & 7;
    const float* w = setid == 0 ? p0 : setid == 1 ? p1 : setid == 2 ? p2 : setid == 3 ? p3
                   : setid == 4 ? p4 : setid == 5 ? p5 : setid == 6 ? p6 : p7;
    float* dst = g_Wt + ((size_t)setid * 32 + blk) * 1152;
    for (int i = threadIdx.x; i < 1152; i += 256) {
        int o = i & 15, r = i >> 4;
        int ci = r / 9, tap = r - ci * 9;
        dst[i] = w[((size_t)(ocb * 16 + o) * 64 + cc * 8 + ci) * 9 + tap];
    }
}

// g_C1[e] in-place affine   <<<8192,256>>> float4
__global__ void c1_affine_kernel() {
    size_t i = (size_t)blockIdx.x * 256 + threadIdx.x;   // float4 index, 2^21 total
    int e = (int)(i >> 20);
    int c = (int)(i >> 8) & 63;
    float sc = g_scale1[e][c], sh = g_shift1[e][c];
    float4* p = reinterpret_cast<float4*>(&g_C1[0][0]) + i;
    float4 v = *p;
    v.x = fmaf(v.x, sc, sh); v.y = fmaf(v.y, sc, sh);
    v.z = fmaf(v.z, sc, sh); v.w = fmaf(v.w, sc, sh);
    *p = v;
}

// --------------------------- conv (16-row strips) ---------------------------
// Stage one 8-ci group's 18-row strip tile (rows strip16-1 .. strip16+16) + weights.
__device__ __forceinline__ void issue_group(uint32_t sInU, uint32_t sWU,
    const float* __restrict__ src, const float* __restrict__ wgrp,
    int b, int cbase, int strip16, int t)
{
#pragma unroll
    for (int j = 0; j < 5; ++j) {
        int idx = t + j * 256;
        if (idx < 1152) {
            int ci  = idx / 144;
            int rem = idx - ci * 144;
            int r = rem >> 3, chunk = rem & 7;
            int gy = strip16 + r - 1;
            if ((unsigned)gy < 32u)
                cpa16(sInU + ((ci * CI_STRIDE + r * 40 + 4 + (chunk << 2)) << 2),
                      src + (((size_t)b * 64 + cbase + ci) << 10) + (gy << 5) + (chunk << 2));
        }
    }
    cpa16(sWU + t * 16, wgrp + t * 4);
    if (t < 32) cpa16(sWU + (256 + t) * 16, wgrp + (256 + t) * 4);
}

// grid 1024: e=bx>>9, b=(bx>>3)&63, strip=(bx>>2)&1, ocb=bx&3
// thread (tx, ty): oc half h=ty&1 (8 oc), rows r0=ty>>1 {+0,+4,+8,+12} (4 pixels)
template <int STAGE, int PAIR>
__global__ __launch_bounds__(256, 3)
void conv_strip_kernel() {
    extern __shared__ float smem[];
    float* sIn   = smem;
    float* sW    = smem + SW_OFF;
    float* sStat = smem + SSTAT_OFF;
    uint32_t sInU = (uint32_t)__cvta_generic_to_shared(sIn);
    uint32_t sWU  = (uint32_t)__cvta_generic_to_shared(sW);

    const int bx    = blockIdx.x;
    const int e     = bx >> 9;
    const int b     = (bx >> 3) & 63;
    const int strip = (bx >> 2) & 1;
    const int ocb   = bx & 3;
    const int oc0   = ocb << 4;
    const int strip16 = strip << 4;
    const int t  = threadIdx.x;
    const int tx = t & 31, ty = t >> 5;
    const int lane = tx, wid = ty;
    const int h  = ty & 1;         // oc half
    const int r0 = ty >> 1;        // row base (0..3)

    const float* src = (STAGE == 2) ? g_C1[e]
                     : (PAIR == 0)  ? g_Xr
                     : (e ? g_N2r : g_N1r);
    const int setid = PAIR * 4 + (STAGE - 1) * 2 + e;
    const float* wt = g_Wt + ((size_t)setid * 32 + ocb * 8) * 1152;
    float* gPe = g_P[e];

    // zero whole input tile once (OOB rows + col halos stay zero; data cells
    // always rewritten by cp.async each group)
    for (int i = t; i < SW_OFF / 4; i += 256)
        reinterpret_cast<float4*>(sIn)[i] = make_float4(0.f, 0.f, 0.f, 0.f);
    __syncthreads();

    u64 acc2[4][4];                // [pixel j][oc pair o2]
#pragma unroll
    for (int j = 0; j < 4; ++j)
#pragma unroll
        for (int o2 = 0; o2 < 4; ++o2) acc2[j][o2] = 0ull;

    issue_group(sInU, sWU, src, wt, b, 0, strip16, t);
    cpa_commit();

#pragma unroll 1
    for (int cc = 0; cc < 8; ++cc) {
        const int cur = cc & 1;
        if (cc < 7) {
            issue_group(sInU + (cur ^ 1) * (BUF_STRIDE * 4), sWU + (cur ^ 1) * (1152 * 4),
                        src, wt + (cc + 1) * 1152, b, (cc + 1) << 3, strip16, t);
            cpa_commit();
            cpa_wait<1>();
        } else {
            cpa_wait<0>();
        }
        __syncthreads();

        const float* buf = sIn + cur * BUF_STRIDE;
        const float* wb  = sW + cur * 1152;
#pragma unroll 1
        for (int ci = 0; ci < 8; ++ci) {
            const float* bci = buf + ci * CI_STRIDE;
#pragma unroll
            for (int ky = 0; ky < 3; ++ky) {
#pragma unroll
                for (int kx = 0; kx < 3; ++kx) {
                    // this thread's 8 oc weights = 2x LDS.128 (broadcast in warp)
                    const ulonglong2* w128 = reinterpret_cast<const ulonglong2*>(
                        wb + ((ci * 9 + ky * 3 + kx) << 4) + (h << 3));
                    u64 wp[4];
                    ulonglong2 q0 = w128[0]; wp[0] = q0.x; wp[1] = q0.y;
                    ulonglong2 q1 = w128[1]; wp[2] = q1.x; wp[3] = q1.y;
#pragma unroll
                    for (int j = 0; j < 4; ++j) {
                        float iv = bci[(r0 + (j << 2) + ky) * 40 + tx + kx + 3];
                        u64 iv2 = pack2(iv, iv);
#pragma unroll
                        for (int o2 = 0; o2 < 4; ++o2)
                            acc2[j][o2] = fma2(iv2, wp[o2], acc2[j][o2]);
                    }
                }
            }
        }

        if (STAGE == 2) {      // prefix boundary: emit P_cc + stats
            float v[16];
#pragma unroll
            for (int o = 0; o < 16; ++o) v[o] = 0.f;
#pragma unroll
            for (int j = 0; j < 4; ++j) {
                int pix = ((strip16 + r0 + (j << 2)) << 5) + tx;
#pragma unroll
                for (int o2 = 0; o2 < 4; ++o2) {
                    float2 pv = unpack2(acc2[j][o2]);
                    int oc = oc0 + (h << 3) + (o2 << 1);
                    size_t base = (((size_t)cc * 64 + b) * 64 + oc) * 1024 + pix;
                    gPe[base]        = pv.x;
                    gPe[base + 1024] = pv.y;
                    v[2 * o2]         += pv.x;
                    v[8 + 2 * o2]     += pv.x * pv.x;
                    v[2 * o2 + 1]     += pv.y;
                    v[8 + 2 * o2 + 1] += pv.y * pv.y;
                }
            }
            float rv = warp_reduce16(v, lane);
            if (lane < 16) sStat[cur * 128 + (wid << 4) + lane] = rv;
        }
        __syncthreads();
        if (STAGE == 2 && t < 32) {
            // t<16: s for oc_local=t ; t>=16: q for oc_local=t-16
            int ocl = t & 15, isq = t >> 4;
            int h2 = ocl >> 3, jj = ocl & 7;
            float s = 0.f;
#pragma unroll
            for (int wset = 0; wset < 4; ++wset)
                s += sStat[cur * 128 + ((h2 + 2 * wset) << 4) + isq * 8 + jj];
            float qv = __shfl_down_sync(0xffffffffu, s, 16);
            if (t < 16)
                g_part2[e][((size_t)cc * 64 + oc0 + ocl) * 128 + (b << 1) + strip] =
                    make_float2(s, qv);
        }
    }

    if (STAGE == 1) {
        float v[16];
#pragma unroll
        for (int o = 0; o < 16; ++o) v[o] = 0.f;
        float* gC = g_C1[e];
#pragma unroll
        for (int j = 0; j < 4; ++j) {
            int pix = ((strip16 + r0 + (j << 2)) << 5) + tx;
#pragma unroll
            for (int o2 = 0; o2 < 4; ++o2) {
                float2 pv = unpack2(acc2[j][o2]);
                int oc = oc0 + (h << 3) + (o2 << 1);
                size_t base = (((size_t)b * 64 + oc) << 10) + pix;
                gC[base]        = pv.x;
                gC[base + 1024] = pv.y;
                v[2 * o2]         += pv.x;
                v[8 + 2 * o2]     += pv.x * pv.x;
                v[2 * o2 + 1]     += pv.y;
                v[8 + 2 * o2 + 1] += pv.y * pv.y;
            }
        }
        float rv = warp_reduce16(v, lane);
        if (lane < 16) sStat[(wid << 4) + lane] = rv;
        __syncthreads();
        if (t < 32) {
            int ocl = t & 15, isq = t >> 4;
            int h2 = ocl >> 3, jj = ocl & 7;
            float s = 0.f;
#pragma unroll
            for (int wset = 0; wset < 4; ++wset)
                s += sStat[((h2 + 2 * wset) << 4) + isq * 8 + jj];
            float qv = __shfl_down_sync(0xffffffffu, s, 16);
            if (t < 16)
                g_part1[e][(oc0 + ocl) * 128 + (b << 1) + strip] = make_float2(s, qv);
        }
    }
}

// ------------------------------- finalizers --------------------------------
__global__ void fin1_pair() {   // <<<1,128>>>
    int e = threadIdx.x >> 6, c = threadIdx.x & 63;
    float s = 0.f, q = 0.f;
    for (int j = 0; j < 128; ++j) { float2 v = g_part1[e][c * 128 + j]; s += v.x; q += v.y; }
    const float invN = 1.f / 65536.f;
    float mu = s * invN;
    float var = q * invN - mu * mu;
    float sc = rsqrtf(var + EPSV) * g_m1v[c];
    g_scale1[e][c] = sc;
    g_shift1[e][c] = -mu * sc;
}

__global__ void fin2_pair(const float* __restrict__ a2) {   // <<<1,128>>>
    int e = threadIdx.x >> 6, c = threadIdx.x & 63;
    const float invN = 1.f / 65536.f;
    float bias = 0.f;
    for (int k = 0; k < 8; ++k) {
        float s = 0.f, q = 0.f;
        for (int j = 0; j < 128; ++j) {
            float2 v = g_part2[e][((size_t)k * 64 + c) * 128 + j]; s += v.x; q += v.y;
        }
        float mu = s * invN;
        float var = q * invN - mu * mu;
        float wk = a2[k] * rsqrtf(var + EPSV);
        g_scaleP[e][k * 64 + c] = wk;
        bias -= wk * mu;
    }
    g_biasP[e][c] = bias;
}

// -------------------------------- combines ---------------------------------
__device__ __forceinline__ float4 comb_acc(int E, int b, int c, int p0) {
    float bias = g_biasP[E][c];
    float4 acc = make_float4(bias, bias, bias, bias);
#pragma unroll
    for (int k = 0; k < 8; ++k) {
        float sp = g_scaleP[E][k * 64 + c];
        float4 v = *reinterpret_cast<const float4*>(
            &g_P[E][(((size_t)k * 64 + b) * 64 + c) * 1024 + p0]);
        acc.x = fmaf(sp, v.x, acc.x); acc.y = fmaf(sp, v.y, acc.y);
        acc.z = fmaf(sp, v.z, acc.z); acc.w = fmaf(sp, v.w, acc.w);
    }
    return acc;
}

// n1: relu -> g_N1r (raw kept in smem); n2 = comb1 + avgpool3(n1)*cm, relu -> g_N2r
__global__ __launch_bounds__(256)
void combine01_kernel() {   // <<<4096,256>>>
    __shared__ float sN[1024];
    int bc = blockIdx.x, b = bc >> 6, c = bc & 63;
    int p0 = threadIdx.x << 2;
    size_t base = ((size_t)b * 64 + c) << 10;

    float4 a0 = comb_acc(0, b, c, p0);
    *reinterpret_cast<float4*>(&sN[p0]) = a0;
    a0.x = fmaxf(a0.x, 0.f); a0.y = fmaxf(a0.y, 0.f);
    a0.z = fmaxf(a0.z, 0.f); a0.w = fmaxf(a0.w, 0.f);
    *reinterpret_cast<float4*>(&g_N1r[base + p0]) = a0;
    __syncthreads();

    float4 a1 = comb_acc(1, b, c, p0);
    float cmv = g_cmv[c];
    int y = p0 >> 5, x = p0 & 31;
    int y0 = max(y - 1, 0), y1 = min(y + 1, 31);
    float rs[6];
#pragma unroll
    for (int j = 0; j < 6; ++j) {
        int xx = x - 1 + j;
        float v = 0.f;
        if ((unsigned)xx < 32u)
            for (int yy = y0; yy <= y1; ++yy) v += sN[(yy << 5) + xx];
        rs[j] = v;
    }
    float nr = (float)(y1 - y0 + 1);
    float pool[4];
#pragma unroll
    for (int i = 0; i < 4; ++i) {
        int xi = x + i;
        int c0 = max(xi - 1, 0), c1 = min(xi + 1, 31);
        pool[i] = (rs[i] + rs[i + 1] + rs[i + 2]) / (nr * (float)(c1 - c0 + 1));
    }
    a1.x = fmaxf(fmaf(pool[0], cmv, a1.x), 0.f);
    a1.y = fmaxf(fmaf(pool[1], cmv, a1.y), 0.f);
    a1.z = fmaxf(fmaf(pool[2], cmv, a1.z), 0.f);
    a1.w = fmaxf(fmaf(pool[3], cmv, a1.w), 0.f);
    *reinterpret_cast<float4*>(&g_N2r[base + p0]) = a1;
}

__global__ __launch_bounds__(256)
void combineF_kernel(const float* __restrict__ xin, float* __restrict__ out) {
    int bc = blockIdx.x, b = bc >> 6, c = bc & 63;
    int p0 = threadIdx.x << 2;
    size_t base = ((size_t)b * 64 + c) << 10;
    float4 a0 = comb_acc(0, b, c, p0);
    float4 a1 = comb_acc(1, b, c, p0);
    float cmv = g_cmv[c];
    float4 xv = *reinterpret_cast<const float4*>(&xin[base + p0]);
    a0.x += a1.x + xv.x * cmv; a0.y += a1.y + xv.y * cmv;
    a0.z += a1.z + xv.z * cmv; a0.w += a1.w + xv.w * cmv;
    *reinterpret_cast<float4*>(&out[base + p0]) = a0;
}

// ---------------------------------------------------------------------------
extern "C" void kernel_launch(void* const* d_in, const int* in_sizes, int n_in,
                              void* d_out, int out_size) {
    (void)in_sizes; (void)n_in; (void)out_size;
    const float* x    = (const float*)d_in[0];
    const float* a1   = (const float*)d_in[1];
    const float* a2   = (const float*)d_in[2];
    const float* W1_0 = (const float*)d_in[3];
    const float* W2_0 = (const float*)d_in[4];
    const float* W1_1 = (const float*)d_in[5];
    const float* W2_1 = (const float*)d_in[6];
    const float* W1_4 = (const float*)d_in[7];
    const float* W2_4 = (const float*)d_in[8];
    const float* W1_5 = (const float*)d_in[9];
    const float* W2_5 = (const float*)d_in[10];
    float* out = (float*)d_out;

    cudaFuncSetAttribute(conv_strip_kernel<1, 0>, cudaFuncAttributeMaxDynamicSharedMemorySize, SMEM_BYTES);
    cudaFuncSetAttribute(conv_strip_kernel<2, 0>, cudaFuncAttributeMaxDynamicSharedMemorySize, SMEM_BYTES);
    cudaFuncSetAttribute(conv_strip_kernel<1, 1>, cudaFuncAttributeMaxDynamicSharedMemorySize, SMEM_BYTES);
    cudaFuncSetAttribute(conv_strip_kernel<2, 1>, cudaFuncAttributeMaxDynamicSharedMemorySize, SMEM_BYTES);

    prep_small<<<1, 64>>>(a1, a2);
    wtrans_kernel<<<256, 256>>>(W1_0, W1_1, W2_0, W2_1, W1_4, W1_5, W2_4, W2_5);
    relux_kernel<<<4096, 256>>>(x);

    // pair 0: edges 0 (->n1) and 1 (->n2)
    conv_strip_kernel<1, 0><<<1024, 256, SMEM_BYTES>>>();
    fin1_pair<<<1, 128>>>();
    c1_affine_kernel<<<8192, 256>>>();
    conv_strip_kernel<2, 0><<<1024, 256, SMEM_BYTES>>>();
    fin2_pair<<<1, 128>>>(a2);
    combine01_kernel<<<4096, 256>>>();

    // pair 1: edges 4 (conv(n1)) and 5 (conv(n2))
    conv_strip_kernel<1, 1><<<1024, 256, SMEM_BYTES>>>();
    fin1_pair<<<1, 128>>>();
    c1_affine_kernel<<<8192, 256>>>();
    conv_strip_kernel<2, 1><<<1024, 256, SMEM_BYTES>>>();
    fin2_pair<<<1, 128>>>(a2);
    combineF_kernel<<<4096, 256>>>(x, out);
}

// round 16
// speedup vs baseline: 1.0842x; 1.0842x over previous
#include <cuda_runtime.h>
#include <cuda_fp16.h>
#include <stdint.h>

typedef unsigned long long u64;
#define EPSV 1e-5f

// smem (floats): sIn 2x(8ci x 18rows x 40cols)=11520 | sW 2x1152=2304 | sStat 512
#define CI_STRIDE  720
#define BUF_STRIDE 5760
#define SW_OFF     11520
#define SSTAT_OFF  13824
#define SMEM_FL    14336
#define SMEM_BYTES (SMEM_FL * 4)

__device__ float   g_C1[2][(size_t)64 * 64 * 1024];
__device__ __half2 g_Ph[2][(size_t)8 * 64 * 32 * 1024];   // [k][b][ocpair][pix]
__device__ float   g_Xr [(size_t)64 * 64 * 1024];
__device__ float   g_N1r[(size_t)64 * 64 * 1024];
__device__ float   g_N2r[(size_t)64 * 64 * 1024];
__device__ float2  g_part1[2][64 * 128];          // [c][b*2+strip]
__device__ float2  g_part2[2][8 * 64 * 128];      // [k][c][b*2+strip]
__device__ float   g_scale1[2][64], g_shift1[2][64];
__device__ float   g_scaleP[2][8 * 64];
__device__ float   g_biasP[2][64];
__device__ float   g_m1v[64], g_cmv[64];
__device__ float   g_Wt[(size_t)8 * 32 * 1152];   // [set][ocb*8+cc][r=ci*9+tap][16 oc]

__device__ __forceinline__ u64 fma2(u64 a, u64 b, u64 c) {
    u64 d; asm("fma.rn.f32x2 %0, %1, %2, %3;" : "=l"(d) : "l"(a), "l"(b), "l"(c)); return d;
}
__device__ __forceinline__ u64 pack2(float x, float y) {
    u64 d; asm("mov.b64 %0, {%1, %2};" : "=l"(d) : "f"(x), "f"(y)); return d;
}
__device__ __forceinline__ float2 unpack2(u64 v) {
    float2 r; asm("mov.b64 {%0, %1}, %2;" : "=f"(r.x), "=f"(r.y) : "l"(v)); return r;
}
__device__ __forceinline__ void cpa16(uint32_t s, const float* g) {
    asm volatile("cp.async.cg.shared.global [%0], [%1], 16;" :: "r"(s), "l"(g));
}
__device__ __forceinline__ void cpa_commit() { asm volatile("cp.async.commit_group;"); }
template <int N> __device__ __forceinline__ void cpa_wait() {
    asm volatile("cp.async.wait_group %0;" :: "n"(N));
}

__device__ __forceinline__ void warp_reduce32(float* v, int lane) {
#pragma unroll
    for (int d = 16; d >= 1; d >>= 1)
#pragma unroll
        for (int i = 0; i < d; ++i) {
            float mine = (lane & d) ? v[i + d] : v[i];
            float give = (lane & d) ? v[i]     : v[i + d];
            v[i] = mine + __shfl_xor_sync(0xffffffffu, give, d);
        }
}

// ------------------------------ prep kernels -------------------------------
__global__ void prep_small(const float* __restrict__ a1, const float* __restrict__ a2) {
    int c = threadIdx.x, g = c >> 3;
    float s1 = 0.f, s2 = 0.f;
    for (int i = g; i < 8; ++i) { s1 += a1[i]; s2 += a2[i]; }
    g_m1v[c] = s1; g_cmv[c] = s1 * s2;
}

__global__ void relux_kernel(const float* __restrict__ x) {   // <<<4096,256>>> float4
    size_t i = (size_t)blockIdx.x * 256 + threadIdx.x;
    float4 v = reinterpret_cast<const float4*>(x)[i];
    v.x = fmaxf(v.x, 0.f); v.y = fmaxf(v.y, 0.f);
    v.z = fmaxf(v.z, 0.f); v.w = fmaxf(v.w, 0.f);
    reinterpret_cast<float4*>(g_Xr)[i] = v;
}

// sets: 0:W1_0 1:W1_1 2:W2_0 3:W2_1 4:W1_4 5:W1_5 6:W2_4 7:W2_5
__global__ void wtrans_kernel(const float* p0, const float* p1, const float* p2, const float* p3,
                              const float* p4, const float* p5, const float* p6, const float* p7) {
    int setid = blockIdx.x >> 5;            // <<<256,256>>>
    int blk = blockIdx.x & 31;
    int ocb = blk >> 3, cc = blk & 7;
    const float* w = setid == 0 ? p0 : setid == 1 ? p1 : setid == 2 ? p2 : setid == 3 ? p3
                   : setid == 4 ? p4 : setid == 5 ? p5 : setid == 6 ? p6 : p7;
    float* dst = g_Wt + ((size_t)setid * 32 + blk) * 1152;
    for (int i = threadIdx.x; i < 1152; i += 256) {
        int o = i & 15, r = i >> 4;
        int ci = r / 9, tap = r - ci * 9;
        dst[i] = w[((size_t)(ocb * 16 + o) * 64 + cc * 8 + ci) * 9 + tap];
    }
}

// g_C1[e] in-place affine   <<<8192,256>>> float4
__global__ void c1_affine_kernel() {
    size_t i = (size_t)blockIdx.x * 256 + threadIdx.x;   // float4 index, 2^21 total
    int e = (int)(i >> 20);
    int c = (int)(i >> 8) & 63;
    float sc = g_scale1[e][c], sh = g_shift1[e][c];
    float4* p = reinterpret_cast<float4*>(&g_C1[0][0]) + i;
    float4 v = *p;
    v.x = fmaf(v.x, sc, sh); v.y = fmaf(v.y, sc, sh);
    v.z = fmaf(v.z, sc, sh); v.w = fmaf(v.w, sc, sh);
    *p = v;
}

// --------------------------- conv (16-row strips) ---------------------------
__device__ __forceinline__ void issue_group(uint32_t sInU, uint32_t sWU,
    const float* __restrict__ src, const float* __restrict__ wgrp,
    int b, int cbase, int strip16, int t)
{
#pragma unroll
    for (int j = 0; j < 5; ++j) {
        int idx = t + j * 256;
        if (idx < 1152) {
            int ci  = idx / 144;
            int rem = idx - ci * 144;
            int r = rem >> 3, chunk = rem & 7;
            int gy = strip16 + r - 1;
            if ((unsigned)gy < 32u)
                cpa16(sInU + ((ci * CI_STRIDE + r * 40 + 4 + (chunk << 2)) << 2),
                      src + (((size_t)b * 64 + cbase + ci) << 10) + (gy << 5) + (chunk << 2));
        }
    }
    cpa16(sWU + t * 16, wgrp + t * 4);
    if (t < 32) cpa16(sWU + (256 + t) * 16, wgrp + (256 + t) * 4);
}

// grid 1024: e=bx>>9, b=(bx>>3)&63, strip=(bx>>2)&1, ocb=bx&3
// thread: 2 pixels (rows strip16+ty, strip16+ty+8; col tx) x 16 oc
template <int STAGE, int PAIR>
__global__ __launch_bounds__(256, 3)
void conv_strip_kernel() {
    extern __shared__ float smem[];
    float* sIn   = smem;
    float* sW    = smem + SW_OFF;
    float* sStat = smem + SSTAT_OFF;
    uint32_t sInU = (uint32_t)__cvta_generic_to_shared(sIn);
    uint32_t sWU  = (uint32_t)__cvta_generic_to_shared(sW);

    const int bx    = blockIdx.x;
    const int e     = bx >> 9;
    const int b     = (bx >> 3) & 63;
    const int strip = (bx >> 2) & 1;
    const int ocb   = bx & 3;
    const int oc0   = ocb << 4;
    const int strip16 = strip << 4;
    const int t  = threadIdx.x;
    const int tx = t & 31, ty = t >> 5;
    const int lane = tx, wid = ty;

    const float* src = (STAGE == 2) ? g_C1[e]
                     : (PAIR == 0)  ? g_Xr
                     : (e ? g_N2r : g_N1r);
    const int setid = PAIR * 4 + (STAGE - 1) * 2 + e;
    const float* wt = g_Wt + ((size_t)setid * 32 + ocb * 8) * 1152;
    __half2* gPe = g_Ph[e];

    // zero whole input tile once (OOB rows + col halos stay zero; data cells
    // always rewritten by cp.async each group)
    for (int i = t; i < SW_OFF / 4; i += 256)
        reinterpret_cast<float4*>(sIn)[i] = make_float4(0.f, 0.f, 0.f, 0.f);
    __syncthreads();

    u64 acc2[2][8];
#pragma unroll
    for (int py = 0; py < 2; ++py)
#pragma unroll
        for (int o2 = 0; o2 < 8; ++o2) acc2[py][o2] = 0ull;

    issue_group(sInU, sWU, src, wt, b, 0, strip16, t);
    cpa_commit();

#pragma unroll 1
    for (int cc = 0; cc < 8; ++cc) {
        const int cur = cc & 1;
        if (cc < 7) {
            issue_group(sInU + (cur ^ 1) * (BUF_STRIDE * 4), sWU + (cur ^ 1) * (1152 * 4),
                        src, wt + (cc + 1) * 1152, b, (cc + 1) << 3, strip16, t);
            cpa_commit();
            cpa_wait<1>();
        } else {
            cpa_wait<0>();
        }
        __syncthreads();

        const float* buf = sIn + cur * BUF_STRIDE;
        const float* wb  = sW + cur * 1152;
#pragma unroll 1
        for (int ci = 0; ci < 8; ++ci) {
            const float* bci = buf + ci * CI_STRIDE;
#pragma unroll
            for (int ky = 0; ky < 3; ++ky) {
#pragma unroll
                for (int kx = 0; kx < 3; ++kx) {
                    const ulonglong2* w128 =
                        reinterpret_cast<const ulonglong2*>(wb + ((ci * 9 + ky * 3 + kx) << 4));
                    u64 wp[8];
#pragma unroll
                    for (int q = 0; q < 4; ++q) {
                        ulonglong2 pairq = w128[q];
                        wp[2 * q]     = pairq.x;
                        wp[2 * q + 1] = pairq.y;
                    }
#pragma unroll
                    for (int py = 0; py < 2; ++py) {
                        float iv = bci[(ty + (py << 3) + ky) * 40 + tx + kx + 3];
                        u64 iv2 = pack2(iv, iv);
#pragma unroll
                        for (int o2 = 0; o2 < 8; ++o2)
                            acc2[py][o2] = fma2(iv2, wp[o2], acc2[py][o2]);
                    }
                }
            }
        }

        if (STAGE == 2) {      // prefix boundary: emit P_cc (fp16 pairs) + fp32 stats
            float v[32];
#pragma unroll
            for (int o = 0; o < 32; ++o) v[o] = 0.f;
#pragma unroll
            for (int py = 0; py < 2; ++py) {
                int pix = ((strip16 + ty + (py << 3)) << 5) + tx;
#pragma unroll
                for (int o2 = 0; o2 < 8; ++o2) {
                    float2 pv = unpack2(acc2[py][o2]);
                    int o2g = (ocb << 3) + o2;
                    gPe[(((size_t)cc * 64 + b) * 32 + o2g) * 1024 + pix] =
                        __floats2half2_rn(pv.x, pv.y);
                    v[2 * o2]          += pv.x;
                    v[16 + 2 * o2]     += pv.x * pv.x;
                    v[2 * o2 + 1]      += pv.y;
                    v[16 + 2 * o2 + 1] += pv.y * pv.y;
                }
            }
            warp_reduce32(v, lane);
            sStat[cur * 256 + (wid << 5) + lane] = v[0];
        }
        __syncthreads();
        if (STAGE == 2 && t < 32) {
            float s = 0.f;
#pragma unroll
            for (int ww = 0; ww < 8; ++ww) s += sStat[cur * 256 + (ww << 5) + lane];
            float qv = __shfl_down_sync(0xffffffffu, s, 16);
            if (lane < 16)
                g_part2[e][((size_t)cc * 64 + oc0 + lane) * 128 + (b << 1) + strip] =
                    make_float2(s, qv);
        }
    }

    if (STAGE == 1) {
        float v[32];
#pragma unroll
        for (int o = 0; o < 32; ++o) v[o] = 0.f;
        float* gC = g_C1[e];
#pragma unroll
        for (int py = 0; py < 2; ++py) {
            int pix = ((strip16 + ty + (py << 3)) << 5) + tx;
#pragma unroll
            for (int o2 = 0; o2 < 8; ++o2) {
                float2 pv = unpack2(acc2[py][o2]);
                size_t base = (((size_t)b * 64 + oc0 + (o2 << 1)) << 10) + pix;
                gC[base]        = pv.x;
                gC[base + 1024] = pv.y;
                v[2 * o2]          += pv.x;
                v[16 + 2 * o2]     += pv.x * pv.x;
                v[2 * o2 + 1]      += pv.y;
                v[16 + 2 * o2 + 1] += pv.y * pv.y;
            }
        }
        warp_reduce32(v, lane);
        sStat[(wid << 5) + lane] = v[0];
        __syncthreads();
        if (t < 32) {
            float s = 0.f;
#pragma unroll
            for (int ww = 0; ww < 8; ++ww) s += sStat[(ww << 5) + lane];
            float qv = __shfl_down_sync(0xffffffffu, s, 16);
            if (lane < 16)
                g_part1[e][(oc0 + lane) * 128 + (b << 1) + strip] = make_float2(s, qv);
        }
    }
}

// ------------------------------- finalizers --------------------------------
__global__ void fin1_pair() {   // <<<1,128>>>
    int e = threadIdx.x >> 6, c = threadIdx.x & 63;
    float s = 0.f, q = 0.f;
    for (int j = 0; j < 128; ++j) { float2 v = g_part1[e][c * 128 + j]; s += v.x; q += v.y; }
    const float invN = 1.f / 65536.f;
    float mu = s * invN;
    float var = q * invN - mu * mu;
    float sc = rsqrtf(var + EPSV) * g_m1v[c];
    g_scale1[e][c] = sc;
    g_shift1[e][c] = -mu * sc;
}

__global__ void fin2_pair(const float* __restrict__ a2) {   // <<<1,128>>>
    int e = threadIdx.x >> 6, c = threadIdx.x & 63;
    const float invN = 1.f / 65536.f;
    float bias = 0.f;
    for (int k = 0; k < 8; ++k) {
        float s = 0.f, q = 0.f;
        for (int j = 0; j < 128; ++j) {
            float2 v = g_part2[e][((size_t)k * 64 + c) * 128 + j]; s += v.x; q += v.y;
        }
        float mu = s * invN;
        float var = q * invN - mu * mu;
        float wk = a2[k] * rsqrtf(var + EPSV);
        g_scaleP[e][k * 64 + c] = wk;
        bias -= wk * mu;
    }
    g_biasP[e][c] = bias;
}

// -------------------------------- combines ---------------------------------
// Accumulate 4 pixels x 2 channels (oc pair o2p) from fp16 prefix volumes.
__device__ __forceinline__ void comb_acc2(int E, int b, int o2p, int p0,
                                          float* a0, float* a1) {
    int c0 = o2p << 1;
    float b0 = g_biasP[E][c0], b1 = g_biasP[E][c0 + 1];
#pragma unroll
    for (int i = 0; i < 4; ++i) { a0[i] = b0; a1[i] = b1; }
#pragma unroll
    for (int k = 0; k < 8; ++k) {
        float spe = g_scaleP[E][k * 64 + c0];
        float spo = g_scaleP[E][k * 64 + c0 + 1];
        const __half2* hp = &g_Ph[E][(((size_t)k * 64 + b) * 32 + o2p) * 1024 + p0];
        uint4 raw = *reinterpret_cast<const uint4*>(hp);
        uint32_t rr[4] = {raw.x, raw.y, raw.z, raw.w};
#pragma unroll
        for (int i = 0; i < 4; ++i) {
            float2 f = __half22float2(*reinterpret_cast<__half2*>(&rr[i]));
            a0[i] = fmaf(spe, f.x, a0[i]);
            a1[i] = fmaf(spo, f.y, a1[i]);
        }
    }
}

// n1: relu -> g_N1r (raw kept in smem); n2 = comb1 + avgpool3(n1)*cm, relu -> g_N2r
// grid 2048: b = bx>>5, o2p = bx&31; thread: 4 pixels x 2 channels
__global__ __launch_bounds__(256)
void combine01_kernel() {
    __shared__ float sN[2048];
    int bc = blockIdx.x, b = bc >> 5, o2p = bc & 31;
    int c0 = o2p << 1;
    int t = threadIdx.x;
    int p0 = t << 2;
    size_t base0 = ((size_t)b * 64 + c0) << 10;

    float a0[4], a1[4];
    comb_acc2(0, b, o2p, p0, a0, a1);
#pragma unroll
    for (int i = 0; i < 4; ++i) { sN[p0 + i] = a0[i]; sN[1024 + p0 + i] = a1[i]; }
    float4 r0 = make_float4(fmaxf(a0[0], 0.f), fmaxf(a0[1], 0.f), fmaxf(a0[2], 0.f), fmaxf(a0[3], 0.f));
    float4 r1 = make_float4(fmaxf(a1[0], 0.f), fmaxf(a1[1], 0.f), fmaxf(a1[2], 0.f), fmaxf(a1[3], 0.f));
    *reinterpret_cast<float4*>(&g_N1r[base0 + p0])        = r0;
    *reinterpret_cast<float4*>(&g_N1r[base0 + 1024 + p0]) = r1;
    __syncthreads();

    float e0[4], e1[4];
    comb_acc2(1, b, o2p, p0, e0, e1);
    int y = p0 >> 5, x = p0 & 31;
    int y0 = max(y - 1, 0), y1 = min(y + 1, 31);
    float nr = (float)(y1 - y0 + 1);
#pragma unroll
    for (int ch = 0; ch < 2; ++ch) {
        const float* sc = sN + ch * 1024;
        float cmv = g_cmv[c0 + ch];
        float rs[6];
#pragma unroll
        for (int j = 0; j < 6; ++j) {
            int xx = x - 1 + j;
            float v = 0.f;
            if ((unsigned)xx < 32u)
                for (int yy = y0; yy <= y1; ++yy) v += sc[(yy << 5) + xx];
            rs[j] = v;
        }
        float* ee = ch ? e1 : e0;
#pragma unroll
        for (int i = 0; i < 4; ++i) {
            int xi = x + i;
            int cc0 = max(xi - 1, 0), cc1 = min(xi + 1, 31);
            float pool = (rs[i] + rs[i + 1] + rs[i + 2]) / (nr * (float)(cc1 - cc0 + 1));
            ee[i] = fmaxf(fmaf(pool, cmv, ee[i]), 0.f);
        }
    }
    *reinterpret_cast<float4*>(&g_N2r[base0 + p0]) =
        make_float4(e0[0], e0[1], e0[2], e0[3]);
    *reinterpret_cast<float4*>(&g_N2r[base0 + 1024 + p0]) =
        make_float4(e1[0], e1[1], e1[2], e1[3]);
}

// out = comb(E=0) + comb(E=1) + x*cm   grid 2048
__global__ __launch_bounds__(256)
void combineF_kernel(const float* __restrict__ xin, float* __restrict__ out) {
    int bc = blockIdx.x, b = bc >> 5, o2p = bc & 31;
    int c0 = o2p << 1;
    int t = threadIdx.x;
    int p0 = t << 2;
    size_t base0 = ((size_t)b * 64 + c0) << 10;

    float a0[4], a1[4], e0[4], e1[4];
    comb_acc2(0, b, o2p, p0, a0, a1);
    comb_acc2(1, b, o2p, p0, e0, e1);
    float cm0 = g_cmv[c0], cm1 = g_cmv[c0 + 1];
    float4 xv0 = *reinterpret_cast<const float4*>(&xin[base0 + p0]);
    float4 xv1 = *reinterpret_cast<const float4*>(&xin[base0 + 1024 + p0]);
    float4 o0 = make_float4(a0[0] + e0[0] + xv0.x * cm0, a0[1] + e0[1] + xv0.y * cm0,
                            a0[2] + e0[2] + xv0.z * cm0, a0[3] + e0[3] + xv0.w * cm0);
    float4 o1 = make_float4(a1[0] + e1[0] + xv1.x * cm1, a1[1] + e1[1] + xv1.y * cm1,
                            a1[2] + e1[2] + xv1.z * cm1, a1[3] + e1[3] + xv1.w * cm1);
    *reinterpret_cast<float4*>(&out[base0 + p0])        = o0;
    *reinterpret_cast<float4*>(&out[base0 + 1024 + p0]) = o1;
}

// ---------------------------------------------------------------------------
extern "C" void kernel_launch(void* const* d_in, const int* in_sizes, int n_in,
                              void* d_out, int out_size) {
    (void)in_sizes; (void)n_in; (void)out_size;
    const float* x    = (const float*)d_in[0];
    const float* a1   = (const float*)d_in[1];
    const float* a2   = (const float*)d_in[2];
    const float* W1_0 = (const float*)d_in[3];
    const float* W2_0 = (const float*)d_in[4];
    const float* W1_1 = (const float*)d_in[5];
    const float* W2_1 = (const float*)d_in[6];
    const float* W1_4 = (const float*)d_in[7];
    const float* W2_4 = (const float*)d_in[8];
    const float* W1_5 = (const float*)d_in[9];
    const float* W2_5 = (const float*)d_in[10];
    float* out = (float*)d_out;

    cudaFuncSetAttribute(conv_strip_kernel<1, 0>, cudaFuncAttributeMaxDynamicSharedMemorySize, SMEM_BYTES);
    cudaFuncSetAttribute(conv_strip_kernel<2, 0>, cudaFuncAttributeMaxDynamicSharedMemorySize, SMEM_BYTES);
    cudaFuncSetAttribute(conv_strip_kernel<1, 1>, cudaFuncAttributeMaxDynamicSharedMemorySize, SMEM_BYTES);
    cudaFuncSetAttribute(conv_strip_kernel<2, 1>, cudaFuncAttributeMaxDynamicSharedMemorySize, SMEM_BYTES);

    prep_small<<<1, 64>>>(a1, a2);
    wtrans_kernel<<<256, 256>>>(W1_0, W1_1, W2_0, W2_1, W1_4, W1_5, W2_4, W2_5);
    relux_kernel<<<4096, 256>>>(x);

    // pair 0: edges 0 (->n1) and 1 (->n2)
    conv_strip_kernel<1, 0><<<1024, 256, SMEM_BYTES>>>();
    fin1_pair<<<1, 128>>>();
    c1_affine_kernel<<<8192, 256>>>();
    conv_strip_kernel<2, 0><<<1024, 256, SMEM_BYTES>>>();
    fin2_pair<<<1, 128>>>(a2);
    combine01_kernel<<<2048, 256>>>();

    // pair 1: edges 4 (conv(n1)) and 5 (conv(n2))
    conv_strip_kernel<1, 1><<<1024, 256, SMEM_BYTES>>>();
    fin1_pair<<<1, 128>>>();
    c1_affine_kernel<<<8192, 256>>>();
    conv_strip_kernel<2, 1><<<1024, 256, SMEM_BYTES>>>();
    fin2_pair<<<1, 128>>>(a2);
    combineF_kernel<<<2048, 256>>>(x, out);
}

// round 17
// speedup vs baseline: 1.2877x; 1.1877x over previous
#include <cuda_runtime.h>
#include <cuda_fp16.h>
#include <stdint.h>

typedef unsigned long long u64;
#define EPSV 1e-5f

// smem (floats): sIn 2x(8ci x 18rows x 40cols)=11520 | sW 2x1152=2304 | sStat 512
#define CI_STRIDE  720
#define BUF_STRIDE 5760
#define SW_OFF     11520
#define SSTAT_OFF  13824
#define SMEM_FL    14336
#define SMEM_BYTES (SMEM_FL * 4)

__device__ float   g_C1[2][(size_t)64 * 64 * 1024];
__device__ __half2 g_Ph[2][(size_t)8 * 64 * 32 * 1024];   // [k][b][ocpair][pix]
__device__ float   g_Xr [(size_t)64 * 64 * 1024];
__device__ float   g_N1r[(size_t)64 * 64 * 1024];
__device__ float   g_N2r[(size_t)64 * 64 * 1024];
__device__ float2  g_part1[2][64 * 128];          // [c][b*2+strip]
__device__ float2  g_part2[2][8 * 64 * 128];      // [k][c][b*2+strip]
__device__ float   g_scale1[2][64], g_shift1[2][64];
__device__ float   g_scaleP[2][8 * 64];
__device__ float   g_wkmu[2][8 * 64];
__device__ float   g_biasP[2][64];
__device__ float   g_m1v[64], g_cmv[64];
__device__ float   g_Wt[(size_t)8 * 32 * 1152];   // [set][ocb*8+cc][r=ci*9+tap][16 oc]

__device__ __forceinline__ u64 fma2(u64 a, u64 b, u64 c) {
    u64 d; asm("fma.rn.f32x2 %0, %1, %2, %3;" : "=l"(d) : "l"(a), "l"(b), "l"(c)); return d;
}
__device__ __forceinline__ u64 pack2(float x, float y) {
    u64 d; asm("mov.b64 %0, {%1, %2};" : "=l"(d) : "f"(x), "f"(y)); return d;
}
__device__ __forceinline__ float2 unpack2(u64 v) {
    float2 r; asm("mov.b64 {%0, %1}, %2;" : "=f"(r.x), "=f"(r.y) : "l"(v)); return r;
}
__device__ __forceinline__ void cpa16(uint32_t s, const float* g) {
    asm volatile("cp.async.cg.shared.global [%0], [%1], 16;" :: "r"(s), "l"(g));
}
__device__ __forceinline__ void cpa_commit() { asm volatile("cp.async.commit_group;"); }
template <int N> __device__ __forceinline__ void cpa_wait() {
    asm volatile("cp.async.wait_group %0;" :: "n"(N));
}

__device__ __forceinline__ void warp_reduce32(float* v, int lane) {
#pragma unroll
    for (int d = 16; d >= 1; d >>= 1)
#pragma unroll
        for (int i = 0; i < d; ++i) {
            float mine = (lane & d) ? v[i + d] : v[i];
            float give = (lane & d) ? v[i]     : v[i + d];
            v[i] = mine + __shfl_xor_sync(0xffffffffu, give, d);
        }
}

// ------------------------------ prep kernels -------------------------------
__global__ void prep_small(const float* __restrict__ a1, const float* __restrict__ a2) {
    int c = threadIdx.x, g = c >> 3;
    float s1 = 0.f, s2 = 0.f;
    for (int i = g; i < 8; ++i) { s1 += a1[i]; s2 += a2[i]; }
    g_m1v[c] = s1; g_cmv[c] = s1 * s2;
}

__global__ void relux_kernel(const float* __restrict__ x) {   // <<<4096,256>>> float4
    size_t i = (size_t)blockIdx.x * 256 + threadIdx.x;
    float4 v = reinterpret_cast<const float4*>(x)[i];
    v.x = fmaxf(v.x, 0.f); v.y = fmaxf(v.y, 0.f);
    v.z = fmaxf(v.z, 0.f); v.w = fmaxf(v.w, 0.f);
    reinterpret_cast<float4*>(g_Xr)[i] = v;
}

// sets: 0:W1_0 1:W1_1 2:W2_0 3:W2_1 4:W1_4 5:W1_5 6:W2_4 7:W2_5
__global__ void wtrans_kernel(const float* p0, const float* p1, const float* p2, const float* p3,
                              const float* p4, const float* p5, const float* p6, const float* p7) {
    int setid = blockIdx.x >> 5;            // <<<256,256>>>
    int blk = blockIdx.x & 31;
    int ocb = blk >> 3, cc = blk & 7;
    const float* w = setid == 0 ? p0 : setid == 1 ? p1 : setid == 2 ? p2 : setid == 3 ? p3
                   : setid == 4 ? p4 : setid == 5 ? p5 : setid == 6 ? p6 : p7;
    float* dst = g_Wt + ((size_t)setid * 32 + blk) * 1152;
    for (int i = threadIdx.x; i < 1152; i += 256) {
        int o = i & 15, r = i >> 4;
        int ci = r / 9, tap = r - ci * 9;
        dst[i] = w[((size_t)(ocb * 16 + o) * 64 + cc * 8 + ci) * 9 + tap];
    }
}

// g_C1[e] in-place affine   <<<8192,256>>> float4
__global__ void c1_affine_kernel() {
    size_t i = (size_t)blockIdx.x * 256 + threadIdx.x;   // float4 index, 2^21 total
    int e = (int)(i >> 20);
    int c = (int)(i >> 8) & 63;
    float sc = g_scale1[e][c], sh = g_shift1[e][c];
    float4* p = reinterpret_cast<float4*>(&g_C1[0][0]) + i;
    float4 v = *p;
    v.x = fmaf(v.x, sc, sh); v.y = fmaf(v.y, sc, sh);
    v.z = fmaf(v.z, sc, sh); v.w = fmaf(v.w, sc, sh);
    *p = v;
}

// --------------------------- conv (16-row strips) ---------------------------
__device__ __forceinline__ void issue_group(uint32_t sInU, uint32_t sWU,
    const float* __restrict__ src, const float* __restrict__ wgrp,
    int b, int cbase, int strip16, int t)
{
#pragma unroll
    for (int j = 0; j < 5; ++j) {
        int idx = t + j * 256;
        if (idx < 1152) {
            int ci  = idx / 144;
            int rem = idx - ci * 144;
            int r = rem >> 3, chunk = rem & 7;
            int gy = strip16 + r - 1;
            if ((unsigned)gy < 32u)
                cpa16(sInU + ((ci * CI_STRIDE + r * 40 + 4 + (chunk << 2)) << 2),
                      src + (((size_t)b * 64 + cbase + ci) << 10) + (gy << 5) + (chunk << 2));
        }
    }
    cpa16(sWU + t * 16, wgrp + t * 4);
    if (t < 32) cpa16(sWU + (256 + t) * 16, wgrp + (256 + t) * 4);
}

// grid 1024: e=bx>>9, b=(bx>>3)&63, strip=(bx>>2)&1, ocb=bx&3
// thread: 2 pixels (rows strip16+ty, strip16+ty+8; col tx) x 16 oc
template <int STAGE, int PAIR>
__global__ __launch_bounds__(256, 3)
void conv_strip_kernel() {
    extern __shared__ float smem[];
    float* sIn   = smem;
    float* sW    = smem + SW_OFF;
    float* sStat = smem + SSTAT_OFF;
    uint32_t sInU = (uint32_t)__cvta_generic_to_shared(sIn);
    uint32_t sWU  = (uint32_t)__cvta_generic_to_shared(sW);

    const int bx    = blockIdx.x;
    const int e     = bx >> 9;
    const int b     = (bx >> 3) & 63;
    const int strip = (bx >> 2) & 1;
    const int ocb   = bx & 3;
    const int oc0   = ocb << 4;
    const int strip16 = strip << 4;
    const int t  = threadIdx.x;
    const int tx = t & 31, ty = t >> 5;
    const int lane = tx, wid = ty;

    const float* src = (STAGE == 2) ? g_C1[e]
                     : (PAIR == 0)  ? g_Xr
                     : (e ? g_N2r : g_N1r);
    const int setid = PAIR * 4 + (STAGE - 1) * 2 + e;
    const float* wt = g_Wt + ((size_t)setid * 32 + ocb * 8) * 1152;
    __half2* gPe = g_Ph[e];

    // zero whole input tile once (OOB rows + col halos stay zero; data cells
    // always rewritten by cp.async each group)
    for (int i = t; i < SW_OFF / 4; i += 256)
        reinterpret_cast<float4*>(sIn)[i] = make_float4(0.f, 0.f, 0.f, 0.f);
    __syncthreads();

    u64 acc2[2][8];
#pragma unroll
    for (int py = 0; py < 2; ++py)
#pragma unroll
        for (int o2 = 0; o2 < 8; ++o2) acc2[py][o2] = 0ull;

    issue_group(sInU, sWU, src, wt, b, 0, strip16, t);
    cpa_commit();

#pragma unroll 1
    for (int cc = 0; cc < 8; ++cc) {
        const int cur = cc & 1;
        if (cc < 7) {
            issue_group(sInU + (cur ^ 1) * (BUF_STRIDE * 4), sWU + (cur ^ 1) * (1152 * 4),
                        src, wt + (cc + 1) * 1152, b, (cc + 1) << 3, strip16, t);
            cpa_commit();
            cpa_wait<1>();
        } else {
            cpa_wait<0>();
        }
        __syncthreads();

        const float* buf = sIn + cur * BUF_STRIDE;
        const float* wb  = sW + cur * 1152;
#pragma unroll 1
        for (int ci = 0; ci < 8; ++ci) {
            const float* bci = buf + ci * CI_STRIDE;
#pragma unroll
            for (int ky = 0; ky < 3; ++ky) {
#pragma unroll
                for (int kx = 0; kx < 3; ++kx) {
                    const ulonglong2* w128 =
                        reinterpret_cast<const ulonglong2*>(wb + ((ci * 9 + ky * 3 + kx) << 4));
                    u64 wp[8];
#pragma unroll
                    for (int q = 0; q < 4; ++q) {
                        ulonglong2 pairq = w128[q];
                        wp[2 * q]     = pairq.x;
                        wp[2 * q + 1] = pairq.y;
                    }
#pragma unroll
                    for (int py = 0; py < 2; ++py) {
                        float iv = bci[(ty + (py << 3) + ky) * 40 + tx + kx + 3];
                        u64 iv2 = pack2(iv, iv);
#pragma unroll
                        for (int o2 = 0; o2 < 8; ++o2)
                            acc2[py][o2] = fma2(iv2, wp[o2], acc2[py][o2]);
                    }
                }
            }
        }

        if (STAGE == 2) {      // prefix boundary: emit P_cc (fp16 pairs) + fp32 stats
            float v[32];
#pragma unroll
            for (int o = 0; o < 32; ++o) v[o] = 0.f;
#pragma unroll
            for (int py = 0; py < 2; ++py) {
                int pix = ((strip16 + ty + (py << 3)) << 5) + tx;
#pragma unroll
                for (int o2 = 0; o2 < 8; ++o2) {
                    float2 pv = unpack2(acc2[py][o2]);
                    int o2g = (ocb << 3) + o2;
                    gPe[(((size_t)cc * 64 + b) * 32 + o2g) * 1024 + pix] =
                        __floats2half2_rn(pv.x, pv.y);
                    v[2 * o2]          += pv.x;
                    v[16 + 2 * o2]     += pv.x * pv.x;
                    v[2 * o2 + 1]      += pv.y;
                    v[16 + 2 * o2 + 1] += pv.y * pv.y;
                }
            }
            warp_reduce32(v, lane);
            sStat[cur * 256 + (wid << 5) + lane] = v[0];
        }
        __syncthreads();
        if (STAGE == 2 && t < 32) {
            float s = 0.f;
#pragma unroll
            for (int ww = 0; ww < 8; ++ww) s += sStat[cur * 256 + (ww << 5) + lane];
            float qv = __shfl_down_sync(0xffffffffu, s, 16);
            if (lane < 16)
                g_part2[e][((size_t)cc * 64 + oc0 + lane) * 128 + (b << 1) + strip] =
                    make_float2(s, qv);
        }
    }

    if (STAGE == 1) {
        float v[32];
#pragma unroll
        for (int o = 0; o < 32; ++o) v[o] = 0.f;
        float* gC = g_C1[e];
#pragma unroll
        for (int py = 0; py < 2; ++py) {
            int pix = ((strip16 + ty + (py << 3)) << 5) + tx;
#pragma unroll
            for (int o2 = 0; o2 < 8; ++o2) {
                float2 pv = unpack2(acc2[py][o2]);
                size_t base = (((size_t)b * 64 + oc0 + (o2 << 1)) << 10) + pix;
                gC[base]        = pv.x;
                gC[base + 1024] = pv.y;
                v[2 * o2]          += pv.x;
                v[16 + 2 * o2]     += pv.x * pv.x;
                v[2 * o2 + 1]      += pv.y;
                v[16 + 2 * o2 + 1] += pv.y * pv.y;
            }
        }
        warp_reduce32(v, lane);
        sStat[(wid << 5) + lane] = v[0];
        __syncthreads();
        if (t < 32) {
            float s = 0.f;
#pragma unroll
            for (int ww = 0; ww < 8; ++ww) s += sStat[(ww << 5) + lane];
            float qv = __shfl_down_sync(0xffffffffu, s, 16);
            if (lane < 16)
                g_part1[e][(oc0 + lane) * 128 + (b << 1) + strip] = make_float2(s, qv);
        }
    }
}

// ------------------------------- finalizers --------------------------------
// Parallel fin1: one block per (e,c) = 128 blocks x 128 threads.
__global__ void fin1_par() {
    __shared__ float ss[4], sq[4];
    int bc = blockIdx.x;
    int e = bc >> 6, c = bc & 63;
    int t = threadIdx.x;
    float2 v = g_part1[e][c * 128 + t];
    float s = v.x, q = v.y;
#pragma unroll
    for (int d = 16; d >= 1; d >>= 1) {
        s += __shfl_xor_sync(0xffffffffu, s, d);
        q += __shfl_xor_sync(0xffffffffu, q, d);
    }
    if ((t & 31) == 0) { ss[t >> 5] = s; sq[t >> 5] = q; }
    __syncthreads();
    if (t == 0) {
        s = ss[0] + ss[1] + ss[2] + ss[3];
        q = sq[0] + sq[1] + sq[2] + sq[3];
        const float invN = 1.f / 65536.f;
        float mu = s * invN;
        float var = q * invN - mu * mu;
        float sc = rsqrtf(var + EPSV) * g_m1v[c];
        g_scale1[e][c] = sc;
        g_shift1[e][c] = -mu * sc;
    }
}

// Parallel fin2 stage a: one block per (e,k,c) = 1024 blocks x 128 threads.
__global__ void fin2a_par(const float* __restrict__ a2) {
    __shared__ float ss[4], sq[4];
    int bc = blockIdx.x;
    int e = bc >> 9, k = (bc >> 6) & 7, c = bc & 63;
    int t = threadIdx.x;
    float2 v = g_part2[e][((size_t)k * 64 + c) * 128 + t];
    float s = v.x, q = v.y;
#pragma unroll
    for (int d = 16; d >= 1; d >>= 1) {
        s += __shfl_xor_sync(0xffffffffu, s, d);
        q += __shfl_xor_sync(0xffffffffu, q, d);
    }
    if ((t & 31) == 0) { ss[t >> 5] = s; sq[t >> 5] = q; }
    __syncthreads();
    if (t == 0) {
        s = ss[0] + ss[1] + ss[2] + ss[3];
        q = sq[0] + sq[1] + sq[2] + sq[3];
        const float invN = 1.f / 65536.f;
        float mu = s * invN;
        float var = q * invN - mu * mu;
        float wk = a2[k] * rsqrtf(var + EPSV);
        g_scaleP[e][k * 64 + c] = wk;
        g_wkmu[e][k * 64 + c] = wk * mu;
    }
}

// fin2 stage b: bias[c] = -sum_k wk*mu   <<<1,128>>>
__global__ void fin2b_par() {
    int e = threadIdx.x >> 6, c = threadIdx.x & 63;
    float bias = 0.f;
#pragma unroll
    for (int k = 0; k < 8; ++k) bias -= g_wkmu[e][k * 64 + c];
    g_biasP[e][c] = bias;
}

// -------------------------------- combines ---------------------------------
// Accumulate 4 pixels x 2 channels (oc pair o2p) from fp16 prefix volumes.
__device__ __forceinline__ void comb_acc2(int E, int b, int o2p, int p0,
                                          float* a0, float* a1) {
    int c0 = o2p << 1;
    float b0 = g_biasP[E][c0], b1 = g_biasP[E][c0 + 1];
#pragma unroll
    for (int i = 0; i < 4; ++i) { a0[i] = b0; a1[i] = b1; }
#pragma unroll
    for (int k = 0; k < 8; ++k) {
        float spe = g_scaleP[E][k * 64 + c0];
        float spo = g_scaleP[E][k * 64 + c0 + 1];
        const __half2* hp = &g_Ph[E][(((size_t)k * 64 + b) * 32 + o2p) * 1024 + p0];
        uint4 raw = *reinterpret_cast<const uint4*>(hp);
        uint32_t rr[4] = {raw.x, raw.y, raw.z, raw.w};
#pragma unroll
        for (int i = 0; i < 4; ++i) {
            float2 f = __half22float2(*reinterpret_cast<__half2*>(&rr[i]));
            a0[i] = fmaf(spe, f.x, a0[i]);
            a1[i] = fmaf(spo, f.y, a1[i]);
        }
    }
}

// n1: relu -> g_N1r (raw kept in smem); n2 = comb1 + avgpool3(n1)*cm, relu -> g_N2r
// grid 2048: b = bx>>5, o2p = bx&31; thread: 4 pixels x 2 channels
__global__ __launch_bounds__(256)
void combine01_kernel() {
    __shared__ float sN[2048];
    int bc = blockIdx.x, b = bc >> 5, o2p = bc & 31;
    int c0 = o2p << 1;
    int t = threadIdx.x;
    int p0 = t << 2;
    size_t base0 = ((size_t)b * 64 + c0) << 10;

    float a0[4], a1[4];
    comb_acc2(0, b, o2p, p0, a0, a1);
#pragma unroll
    for (int i = 0; i < 4; ++i) { sN[p0 + i] = a0[i]; sN[1024 + p0 + i] = a1[i]; }
    float4 r0 = make_float4(fmaxf(a0[0], 0.f), fmaxf(a0[1], 0.f), fmaxf(a0[2], 0.f), fmaxf(a0[3], 0.f));
    float4 r1 = make_float4(fmaxf(a1[0], 0.f), fmaxf(a1[1], 0.f), fmaxf(a1[2], 0.f), fmaxf(a1[3], 0.f));
    *reinterpret_cast<float4*>(&g_N1r[base0 + p0])        = r0;
    *reinterpret_cast<float4*>(&g_N1r[base0 + 1024 + p0]) = r1;
    __syncthreads();

    float e0[4], e1[4];
    comb_acc2(1, b, o2p, p0, e0, e1);
    int y = p0 >> 5, x = p0 & 31;
    int y0 = max(y - 1, 0), y1 = min(y + 1, 31);
    float nr = (float)(y1 - y0 + 1);
#pragma unroll
    for (int ch = 0; ch < 2; ++ch) {
        const float* sc = sN + ch * 1024;
        float cmv = g_cmv[c0 + ch];
        float rs[6];
#pragma unroll
        for (int j = 0; j < 6; ++j) {
            int xx = x - 1 + j;
            float v = 0.f;
            if ((unsigned)xx < 32u)
                for (int yy = y0; yy <= y1; ++yy) v += sc[(yy << 5) + xx];
            rs[j] = v;
        }
        float* ee = ch ? e1 : e0;
#pragma unroll
        for (int i = 0; i < 4; ++i) {
            int xi = x + i;
            int cc0 = max(xi - 1, 0), cc1 = min(xi + 1, 31);
            float pool = (rs[i] + rs[i + 1] + rs[i + 2]) / (nr * (float)(cc1 - cc0 + 1));
            ee[i] = fmaxf(fmaf(pool, cmv, ee[i]), 0.f);
        }
    }
    *reinterpret_cast<float4*>(&g_N2r[base0 + p0]) =
        make_float4(e0[0], e0[1], e0[2], e0[3]);
    *reinterpret_cast<float4*>(&g_N2r[base0 + 1024 + p0]) =
        make_float4(e1[0], e1[1], e1[2], e1[3]);
}

// out = comb(E=0) + comb(E=1) + x*cm   grid 2048
__global__ __launch_bounds__(256)
void combineF_kernel(const float* __restrict__ xin, float* __restrict__ out) {
    int bc = blockIdx.x, b = bc >> 5, o2p = bc & 31;
    int c0 = o2p << 1;
    int t = threadIdx.x;
    int p0 = t << 2;
    size_t base0 = ((size_t)b * 64 + c0) << 10;

    float a0[4], a1[4], e0[4], e1[4];
    comb_acc2(0, b, o2p, p0, a0, a1);
    comb_acc2(1, b, o2p, p0, e0, e1);
    float cm0 = g_cmv[c0], cm1 = g_cmv[c0 + 1];
    float4 xv0 = *reinterpret_cast<const float4*>(&xin[base0 + p0]);
    float4 xv1 = *reinterpret_cast<const float4*>(&xin[base0 + 1024 + p0]);
    float4 o0 = make_float4(a0[0] + e0[0] + xv0.x * cm0, a0[1] + e0[1] + xv0.y * cm0,
                            a0[2] + e0[2] + xv0.z * cm0, a0[3] + e0[3] + xv0.w * cm0);
    float4 o1 = make_float4(a1[0] + e1[0] + xv1.x * cm1, a1[1] + e1[1] + xv1.y * cm1,
                            a1[2] + e1[2] + xv1.z * cm1, a1[3] + e1[3] + xv1.w * cm1);
    *reinterpret_cast<float4*>(&out[base0 + p0])        = o0;
    *reinterpret_cast<float4*>(&out[base0 + 1024 + p0]) = o1;
}

// ---------------------------------------------------------------------------
extern "C" void kernel_launch(void* const* d_in, const int* in_sizes, int n_in,
                              void* d_out, int out_size) {
    (void)in_sizes; (void)n_in; (void)out_size;
    const float* x    = (const float*)d_in[0];
    const float* a1   = (const float*)d_in[1];
    const float* a2   = (const float*)d_in[2];
    const float* W1_0 = (const float*)d_in[3];
    const float* W2_0 = (const float*)d_in[4];
    const float* W1_1 = (const float*)d_in[5];
    const float* W2_1 = (const float*)d_in[6];
    const float* W1_4 = (const float*)d_in[7];
    const float* W2_4 = (const float*)d_in[8];
    const float* W1_5 = (const float*)d_in[9];
    const float* W2_5 = (const float*)d_in[10];
    float* out = (float*)d_out;

    cudaFuncSetAttribute(conv_strip_kernel<1, 0>, cudaFuncAttributeMaxDynamicSharedMemorySize, SMEM_BYTES);
    cudaFuncSetAttribute(conv_strip_kernel<2, 0>, cudaFuncAttributeMaxDynamicSharedMemorySize, SMEM_BYTES);
    cudaFuncSetAttribute(conv_strip_kernel<1, 1>, cudaFuncAttributeMaxDynamicSharedMemorySize, SMEM_BYTES);
    cudaFuncSetAttribute(conv_strip_kernel<2, 1>, cudaFuncAttributeMaxDynamicSharedMemorySize, SMEM_BYTES);

    prep_small<<<1, 64>>>(a1, a2);
    wtrans_kernel<<<256, 256>>>(W1_0, W1_1, W2_0, W2_1, W1_4, W1_5, W2_4, W2_5);
    relux_kernel<<<4096, 256>>>(x);

    // pair 0: edges 0 (->n1) and 1 (->n2)
    conv_strip_kernel<1, 0><<<1024, 256, SMEM_BYTES>>>();
    fin1_par<<<128, 128>>>();
    c1_affine_kernel<<<8192, 256>>>();
    conv_strip_kernel<2, 0><<<1024, 256, SMEM_BYTES>>>();
    fin2a_par<<<1024, 128>>>(a2);
    fin2b_par<<<1, 128>>>();
    combine01_kernel<<<2048, 256>>>();

    // pair 1: edges 4 (conv(n1)) and 5 (conv(n2))
    conv_strip_kernel<1, 1><<<1024, 256, SMEM_BYTES>>>();
    fin1_par<<<128, 128>>>();
    c1_affine_kernel<<<8192, 256>>>();
    conv_strip_kernel<2, 1><<<1024, 256, SMEM_BYTES>>>();
    fin2a_par<<<1024, 128>>>(a2);
    fin2b_par<<<1, 128>>>();
    combineF_kernel<<<2048, 256>>>(x, out);
}